// round 16
// baseline (speedup 1.0000x reference)
#include <cuda_runtime.h>
#include <cuda_fp16.h>
#include <cuda_bf16.h>
#include <cstdint>

// NF4 codebook (float32, matches bitsandbytes / reference exactly)
static __device__ __constant__ float NF4_TBL[16] = {
    -1.0f, -0.6961928009986877f, -0.5250730514526367f, -0.39491748809814453f,
    -0.28444138169288635f, -0.18477343022823334f, -0.09105003625154495f, 0.0f,
    0.07958029955625534f, 0.16093020141124725f, 0.24611230194568634f,
    0.33791524171829224f, 0.4407098591327667f, 0.5626170039176941f,
    0.7229568362236023f, 1.0f
};

#define REPS  16    // lane&15 replication -> conflict-free LDS.64 (row = 128B)
#define NROWS 128   // power of two; bucket extraction masks to this range
#define NSM   148   // sm_100a B200
#define CTAS_PER_SM 4

static __device__ __forceinline__ float red4(const float4& v) {
    return fmaxf(fmaxf(fabsf(v.x), fabsf(v.y)), fmaxf(fabsf(v.z), fabsf(v.w)));
}

__global__ void __launch_bounds__(256, 4)
nf4_qdq_kernel(const float* __restrict__ x, float* __restrict__ out, int nblk) {
    // entry: low 32 bits = fp32 boundary_t (exact compare),
    //        high 32 bits = packed half2 {lo, hi} codebook values
    __shared__ unsigned long long lut[NROWS * REPS];   // 16 KB
    __shared__ unsigned long long entry[NROWS];        // staging

    // ---- phase 1: thread i computes entry i (conflict-free STS) ----
    {
        int i = threadIdx.x;
        if (i < NROWS) {
            unsigned long long raw = 0ull;
            if (i < 65) {
                float loEdge = (float)i - 0.5f;   // bucket i covers t in [i-.5, i+.5)
                float hiEdge = (float)i + 0.5f;
                int lo = 0, hi = 0;
#pragma unroll
                for (int j = 0; j < 15; j++) {
                    float mt = fmaf((NF4_TBL[j] + NF4_TBL[j + 1]) * 0.5f, 32.0f, 32.0f);
                    lo += (mt < loEdge);
                    hi += (mt < hiEdge);
                }
                float bnd = 3.0e38f;
                if (hi > lo)  // at most one midpoint per bucket (min gap 2.73 > 1.0)
                    bnd = fmaf((NF4_TBL[lo] + NF4_TBL[lo + 1]) * 0.5f, 32.0f, 32.0f);
                unsigned lo16 = __half_as_ushort(__float2half_rn(NF4_TBL[lo]));
                unsigned hi16 = __half_as_ushort(__float2half_rn(NF4_TBL[hi]));
                raw = ((unsigned long long)((hi16 << 16) | lo16) << 32)
                    | (unsigned)__float_as_int(bnd);
            }
            entry[i] = raw;
        }
    }
    __syncthreads();

    // ---- phase 2: replicate 16x (broadcast reads, consecutive-lane writes;
    // both conflict-free -- R8 lesson: column-pattern STS = 32-way conflict) ----
    for (int d = threadIdx.x; d < NROWS * REPS; d += 256)
        lut[d] = entry[d >> 4];
    __syncthreads();

    int lane = threadIdx.x & 31;
    const char* __restrict__ lutl = reinterpret_cast<const char*>(lut) + (lane & 15) * 8;

    // |x| <= am => t in [0,64+eps]; m = t + 2^23 has bits 0x4B000000 + bi with
    // bi in [0,64]. (bits << 7) & 0x3FFF == bi*128 exactly (0x4B000000 lands on
    // bit 31, masked; bi*128 <= 0x2000). Addresses stay in [0,16KB).
    auto q = [&](float xv, float s2, float am) -> float {
        float t = fmaf(xv, s2, 32.0f);
        float m = t + 8388608.0f;
        unsigned off = (((unsigned)__float_as_int(m)) << 7) & 0x3FFFu;
        unsigned long long raw = *reinterpret_cast<const unsigned long long*>(lutl + off);
        float bnd = __uint_as_float((unsigned)raw);
        unsigned codes = (unsigned)(raw >> 32);
        unsigned s = codes >> ((t > bnd) ? 16 : 0);   // pick hi or lo half
        float v = __half2float(__ushort_as_half((unsigned short)s));
        return v * am;                                 // NF4[idx] (fp16) * absmax
    };

    // ---- persistent grid-stride over block-PAIRS: one wave, no wave
    // transitions, loads of iteration i+1 issue right behind the stores of
    // iteration i. Per-iteration body identical to the proven R14 pipeline. ----
    int npair = (nblk + 1) >> 1;
    int wstride = gridDim.x * 8;
    for (int gw = blockIdx.x * 8 + (threadIdx.x >> 5); gw < npair; gw += wstride) {
        int blk0 = gw * 2;
        int blk1 = blk0 + 1;
        bool has1 = (blk1 < nblk);

        const float4* __restrict__ xi0 = reinterpret_cast<const float4*>(x) + (size_t)blk0 * 128 + lane;
        const float4* __restrict__ xi1 = reinterpret_cast<const float4*>(x) + (size_t)(has1 ? blk1 : blk0) * 128 + lane;
        float4* __restrict__ xo0 = reinterpret_cast<float4*>(out) + (size_t)blk0 * 128 + lane;
        float4* __restrict__ xo1 = reinterpret_cast<float4*>(out) + (size_t)blk1 * 128 + lane;

        float4 a0 = __ldcs(xi0 + 0);
        float4 b0 = __ldcs(xi0 + 32);
        float4 c0 = __ldcs(xi0 + 64);
        float4 d0 = __ldcs(xi0 + 96);
        float4 a1 = __ldcs(xi1 + 0);
        float4 b1 = __ldcs(xi1 + 32);
        float4 c1 = __ldcs(xi1 + 64);
        float4 d1 = __ldcs(xi1 + 96);

        // absmax via hardware REDUX (bits of non-negative floats are monotone)
        float tm0 = fmaxf(fmaxf(red4(a0), red4(b0)), fmaxf(red4(c0), red4(d0)));
        float tm1 = fmaxf(fmaxf(red4(a1), red4(b1)), fmaxf(red4(c1), red4(d1)));
        float am0 = __uint_as_float(__reduce_max_sync(0xffffffffu, __float_as_uint(tm0)));
        float am1 = __uint_as_float(__reduce_max_sync(0xffffffffu, __float_as_uint(tm1)));
        float s20 = (am0 > 0.0f) ? (32.0f / am0) : 0.0f;
        float s21 = (am1 > 0.0f) ? (32.0f / am1) : 0.0f;

        // ---- block 0 ----
        a0.x = q(a0.x, s20, am0); a0.y = q(a0.y, s20, am0); a0.z = q(a0.z, s20, am0); a0.w = q(a0.w, s20, am0);
        b0.x = q(b0.x, s20, am0); b0.y = q(b0.y, s20, am0); b0.z = q(b0.z, s20, am0); b0.w = q(b0.w, s20, am0);
        c0.x = q(c0.x, s20, am0); c0.y = q(c0.y, s20, am0); c0.z = q(c0.z, s20, am0); c0.w = q(c0.w, s20, am0);
        d0.x = q(d0.x, s20, am0); d0.y = q(d0.y, s20, am0); d0.z = q(d0.z, s20, am0); d0.w = q(d0.w, s20, am0);
        __stcs(xo0 + 0,  a0);
        __stcs(xo0 + 32, b0);
        __stcs(xo0 + 64, c0);
        __stcs(xo0 + 96, d0);

        // ---- block 1 (data resident since the batched loads) ----
        if (has1) {
            a1.x = q(a1.x, s21, am1); a1.y = q(a1.y, s21, am1); a1.z = q(a1.z, s21, am1); a1.w = q(a1.w, s21, am1);
            b1.x = q(b1.x, s21, am1); b1.y = q(b1.y, s21, am1); b1.z = q(b1.z, s21, am1); b1.w = q(b1.w, s21, am1);
            c1.x = q(c1.x, s21, am1); c1.y = q(c1.y, s21, am1); c1.z = q(c1.z, s21, am1); c1.w = q(c1.w, s21, am1);
            d1.x = q(d1.x, s21, am1); d1.y = q(d1.y, s21, am1); d1.z = q(d1.z, s21, am1); d1.w = q(d1.w, s21, am1);
            __stcs(xo1 + 0,  a1);
            __stcs(xo1 + 32, b1);
            __stcs(xo1 + 64, c1);
            __stcs(xo1 + 96, d1);
        }
    }
}

extern "C" void kernel_launch(void* const* d_in, const int* in_sizes, int n_in,
                              void* d_out, int out_size) {
    const float* x = (const float*)d_in[0];
    float* out = (float*)d_out;
    int n = in_sizes[0];
    int nblk = n / 512;                 // reference requires n % 512 == 0
    int npair = (nblk + 1) / 2;
    int ctas_needed = (npair + 7) / 8;
    int ctas = NSM * CTAS_PER_SM;       // one persistent wave (592)
    if (ctas > ctas_needed) ctas = ctas_needed;
    nf4_qdq_kernel<<<ctas, 256>>>(x, out, nblk);
}

// round 17
// speedup vs baseline: 1.1283x; 1.1283x over previous
#include <cuda_runtime.h>
#include <cuda_fp16.h>
#include <cuda_bf16.h>
#include <cstdint>

// NF4 codebook (float32, matches bitsandbytes / reference exactly)
static __device__ __constant__ float NF4_TBL[16] = {
    -1.0f, -0.6961928009986877f, -0.5250730514526367f, -0.39491748809814453f,
    -0.28444138169288635f, -0.18477343022823334f, -0.09105003625154495f, 0.0f,
    0.07958029955625534f, 0.16093020141124725f, 0.24611230194568634f,
    0.33791524171829224f, 0.4407098591327667f, 0.5626170039176941f,
    0.7229568362236023f, 1.0f
};

#define REPS  16    // lane&15 replication -> conflict-free LDS.64 (row = 128B)
#define NROWS 128   // power of two; bucket extraction masks to this range

static __device__ __forceinline__ float red4(const float4& v) {
    return fmaxf(fmaxf(fabsf(v.x), fabsf(v.y)), fmaxf(fabsf(v.z), fabsf(v.w)));
}

__global__ void __launch_bounds__(256, 4)
nf4_qdq_kernel(const float* __restrict__ x, float* __restrict__ out, int nblk) {
    // entry: low 32 bits = fp32 boundary_t (exact compare),
    //        high 32 bits = packed half2 {lo, hi} codebook values
    __shared__ unsigned long long lut[NROWS * REPS];   // 16 KB
    __shared__ unsigned long long entry[NROWS];        // staging

    // ---- phase 1: thread i computes entry i (conflict-free STS) ----
    {
        int i = threadIdx.x;
        if (i < NROWS) {
            unsigned long long raw = 0ull;
            if (i < 65) {
                float loEdge = (float)i - 0.5f;   // bucket i covers t in [i-.5, i+.5)
                float hiEdge = (float)i + 0.5f;
                int lo = 0, hi = 0;
#pragma unroll
                for (int j = 0; j < 15; j++) {
                    float mt = fmaf((NF4_TBL[j] + NF4_TBL[j + 1]) * 0.5f, 32.0f, 32.0f);
                    lo += (mt < loEdge);
                    hi += (mt < hiEdge);
                }
                float bnd = 3.0e38f;
                if (hi > lo)  // at most one midpoint per bucket (min gap 2.73 > 1.0)
                    bnd = fmaf((NF4_TBL[lo] + NF4_TBL[lo + 1]) * 0.5f, 32.0f, 32.0f);
                unsigned lo16 = __half_as_ushort(__float2half_rn(NF4_TBL[lo]));
                unsigned hi16 = __half_as_ushort(__float2half_rn(NF4_TBL[hi]));
                raw = ((unsigned long long)((hi16 << 16) | lo16) << 32)
                    | (unsigned)__float_as_int(bnd);
            }
            entry[i] = raw;
        }
    }
    __syncthreads();

    // ---- phase 2: replicate 16x (broadcast reads, consecutive-lane writes;
    // both conflict-free -- R8 lesson: column-pattern STS = 32-way conflict) ----
    for (int d = threadIdx.x; d < NROWS * REPS; d += 256)
        lut[d] = entry[d >> 4];
    __syncthreads();

    // ---- TWO NF4 blocks (1024 floats) per warp: batch all 8 LDG.128s first
    // (MLP 8/thread), then process both. Non-persistent: fresh CTAs keep the
    // load stream going across block-pairs (persistent grid-stride regressed). ----
    int gw = blockIdx.x * 8 + (threadIdx.x >> 5);   // pair index
    int blk0 = gw * 2;
    if (blk0 >= nblk) return;
    int blk1 = blk0 + 1;
    bool has1 = (blk1 < nblk);
    int lane = threadIdx.x & 31;

    const float4* __restrict__ xi0 = reinterpret_cast<const float4*>(x) + (size_t)blk0 * 128 + lane;
    const float4* __restrict__ xi1 = reinterpret_cast<const float4*>(x) + (size_t)(has1 ? blk1 : blk0) * 128 + lane;
    float4* __restrict__ xo0 = reinterpret_cast<float4*>(out) + (size_t)blk0 * 128 + lane;
    float4* __restrict__ xo1 = reinterpret_cast<float4*>(out) + (size_t)blk1 * 128 + lane;

    float4 a0 = __ldcs(xi0 + 0);
    float4 b0 = __ldcs(xi0 + 32);
    float4 c0 = __ldcs(xi0 + 64);
    float4 d0 = __ldcs(xi0 + 96);
    float4 a1 = __ldcs(xi1 + 0);
    float4 b1 = __ldcs(xi1 + 32);
    float4 c1 = __ldcs(xi1 + 64);
    float4 d1 = __ldcs(xi1 + 96);

    // ---- block absmaxes via hardware REDUX: per-thread max >= 0, and IEEE
    // bits of non-negative floats are monotone in value -> one REDUX.SYNC.U32
    // replaces the 5-step shfl ladder. Bit-identical result. ----
    float tm0 = fmaxf(fmaxf(red4(a0), red4(b0)), fmaxf(red4(c0), red4(d0)));
    float tm1 = fmaxf(fmaxf(red4(a1), red4(b1)), fmaxf(red4(c1), red4(d1)));
    float am0 = __uint_as_float(__reduce_max_sync(0xffffffffu, __float_as_uint(tm0)));
    float am1 = __uint_as_float(__reduce_max_sync(0xffffffffu, __float_as_uint(tm1)));
    float s20 = (am0 > 0.0f) ? (32.0f / am0) : 0.0f;
    float s21 = (am1 > 0.0f) ? (32.0f / am1) : 0.0f;

    const char* __restrict__ lutl = reinterpret_cast<const char*>(lut) + (lane & 15) * 8;

    // |x| <= am => t in [0,64+eps]; m = t + 2^23 has bits 0x4B000000 + bi with
    // bi in [0,64]. (bits << 7) & 0x3FFF == bi*128 exactly (0x4B000000 lands on
    // bit 31, masked; bi*128 <= 0x2000). Addresses stay in [0,16KB).
    auto q = [&](float xv, float s2, float am) -> float {
        float t = fmaf(xv, s2, 32.0f);
        float m = t + 8388608.0f;
        unsigned off = (((unsigned)__float_as_int(m)) << 7) & 0x3FFFu;
        unsigned long long raw = *reinterpret_cast<const unsigned long long*>(lutl + off);
        float bnd = __uint_as_float((unsigned)raw);
        unsigned codes = (unsigned)(raw >> 32);
        unsigned s = codes >> ((t > bnd) ? 16 : 0);   // pick hi or lo half
        float v = __half2float(__ushort_as_half((unsigned short)s));
        return v * am;                                 // NF4[idx] (fp16) * absmax
    };

    // ---- block 0 ----
    a0.x = q(a0.x, s20, am0); a0.y = q(a0.y, s20, am0); a0.z = q(a0.z, s20, am0); a0.w = q(a0.w, s20, am0);
    b0.x = q(b0.x, s20, am0); b0.y = q(b0.y, s20, am0); b0.z = q(b0.z, s20, am0); b0.w = q(b0.w, s20, am0);
    c0.x = q(c0.x, s20, am0); c0.y = q(c0.y, s20, am0); c0.z = q(c0.z, s20, am0); c0.w = q(c0.w, s20, am0);
    d0.x = q(d0.x, s20, am0); d0.y = q(d0.y, s20, am0); d0.z = q(d0.z, s20, am0); d0.w = q(d0.w, s20, am0);
    __stcs(xo0 + 0,  a0);
    __stcs(xo0 + 32, b0);
    __stcs(xo0 + 64, c0);
    __stcs(xo0 + 96, d0);

    // ---- block 1 (data resident since the batched loads) ----
    if (has1) {
        a1.x = q(a1.x, s21, am1); a1.y = q(a1.y, s21, am1); a1.z = q(a1.z, s21, am1); a1.w = q(a1.w, s21, am1);
        b1.x = q(b1.x, s21, am1); b1.y = q(b1.y, s21, am1); b1.z = q(b1.z, s21, am1); b1.w = q(b1.w, s21, am1);
        c1.x = q(c1.x, s21, am1); c1.y = q(c1.y, s21, am1); c1.z = q(c1.z, s21, am1); c1.w = q(c1.w, s21, am1);
        d1.x = q(d1.x, s21, am1); d1.y = q(d1.y, s21, am1); d1.z = q(d1.z, s21, am1); d1.w = q(d1.w, s21, am1);
        __stcs(xo1 + 0,  a1);
        __stcs(xo1 + 32, b1);
        __stcs(xo1 + 64, c1);
        __stcs(xo1 + 96, d1);
    }
}

extern "C" void kernel_launch(void* const* d_in, const int* in_sizes, int n_in,
                              void* d_out, int out_size) {
    const float* x = (const float*)d_in[0];
    float* out = (float*)d_out;
    int n = in_sizes[0];
    int nblk = n / 512;                 // reference requires n % 512 == 0
    int npair = (nblk + 1) / 2;
    int ctas = (npair + 7) / 8;         // 8 warps (= 8 block-pairs) per CTA
    nf4_qdq_kernel<<<ctas, 256>>>(x, out, nblk);
}